// round 2
// baseline (speedup 1.0000x reference)
#include <cuda_runtime.h>
#include <math.h>

// Problem constants
#define TOKENS 2048      // B*Q
#define HIDK   4096      // 2*HID (input feature dim)
#define QDIM   2048      // H*D
#define KVDIM  512       // KVH*D
#define NH     32
#define NKVH   8
#define HD     64
#define LCK_N  3
#define QLEN   1024
#define BATCH  2

// Scratch (static device globals -- no allocation allowed)
__device__ float g_q[TOKENS * QDIM];      // q projection (rope'd, pre-scaled by 1/8)
__device__ float g_k[TOKENS * KVDIM];     // k projection (rope'd)
__device__ float g_v[TOKENS * KVDIM];     // v projection
__device__ float g_attn[TOKENS * QDIM];   // attention output, token-major [tok][H*D]

// ---------------------------------------------------------------------------
// Generic fp32 SGEMM body: C[M,N] = A[M,K] @ B[N,K]^T
// 128x128 block, 256 threads, 8x8 micro-tile per thread, K-step 8.
// All dims here are multiples of 128/8 so no bounds checks.
// ---------------------------------------------------------------------------
__device__ __forceinline__ void sgemm_body(
    const float* __restrict__ A, const float* __restrict__ Bw,
    float* __restrict__ C, int N, int K, int bx, int by)
{
    __shared__ float As[8][128];
    __shared__ float Bs[8][128];
    const int tid  = threadIdx.x;
    const int m0   = by * 128, n0 = bx * 128;
    const int trow = tid >> 4, tcol = tid & 15;
    const int lrow = tid >> 1, lcol = (tid & 1) * 4;

    float c[8][8];
#pragma unroll
    for (int i = 0; i < 8; i++)
#pragma unroll
        for (int j = 0; j < 8; j++) c[i][j] = 0.f;

    const float* Ap = A  + (size_t)(m0 + lrow) * K + lcol;
    const float* Bp = Bw + (size_t)(n0 + lrow) * K + lcol;

    for (int k0 = 0; k0 < K; k0 += 8) {
        float4 av = *(const float4*)(Ap + k0);
        float4 bv = *(const float4*)(Bp + k0);
        __syncthreads();
        As[lcol + 0][lrow] = av.x; As[lcol + 1][lrow] = av.y;
        As[lcol + 2][lrow] = av.z; As[lcol + 3][lrow] = av.w;
        Bs[lcol + 0][lrow] = bv.x; Bs[lcol + 1][lrow] = bv.y;
        Bs[lcol + 2][lrow] = bv.z; Bs[lcol + 3][lrow] = bv.w;
        __syncthreads();
#pragma unroll
        for (int kk = 0; kk < 8; kk++) {
            float4 a0 = *(const float4*)&As[kk][trow * 8];
            float4 a1 = *(const float4*)&As[kk][trow * 8 + 4];
            float4 b0 = *(const float4*)&Bs[kk][tcol * 8];
            float4 b1 = *(const float4*)&Bs[kk][tcol * 8 + 4];
            float ar[8] = {a0.x, a0.y, a0.z, a0.w, a1.x, a1.y, a1.z, a1.w};
            float br[8] = {b0.x, b0.y, b0.z, b0.w, b1.x, b1.y, b1.z, b1.w};
#pragma unroll
            for (int i = 0; i < 8; i++)
#pragma unroll
                for (int j = 0; j < 8; j++)
                    c[i][j] = fmaf(ar[i], br[j], c[i][j]);
        }
    }
#pragma unroll
    for (int i = 0; i < 8; i++) {
        float* Cp = C + (size_t)(m0 + trow * 8 + i) * N + n0 + tcol * 8;
        *(float4*)(Cp)     = make_float4(c[i][0], c[i][1], c[i][2], c[i][3]);
        *(float4*)(Cp + 4) = make_float4(c[i][4], c[i][5], c[i][6], c[i][7]);
    }
}

__global__ __launch_bounds__(256, 2)
void sgemm_q_kernel(const float* __restrict__ hidden, const float* __restrict__ qw) {
    sgemm_body(hidden, qw, g_q, QDIM, HIDK, blockIdx.x, blockIdx.y);
}

__global__ __launch_bounds__(256, 2)
void sgemm_kv_kernel(const float* __restrict__ hidden,
                     const float* __restrict__ kw, const float* __restrict__ vw) {
    if (blockIdx.z == 0) sgemm_body(hidden, kw, g_k, KVDIM, HIDK, blockIdx.x, blockIdx.y);
    else                 sgemm_body(hidden, vw, g_v, KVDIM, HIDK, blockIdx.x, blockIdx.y);
}

__global__ __launch_bounds__(256, 2)
void sgemm_o_kernel(const float* __restrict__ ow, float* __restrict__ out) {
    sgemm_body(g_attn, ow, out, QDIM /*HID out*/, QDIM /*K = H*D*/, blockIdx.x, blockIdx.y);
}

// ---------------------------------------------------------------------------
// RoPE (in place on g_q / g_k). Also folds the 1/sqrt(D)=0.125 attention
// scale into q. Double-precision trig for exact range reduction at angles
// up to ~1027 rad.
// ---------------------------------------------------------------------------
__global__ void rope_kernel(const int* __restrict__ pos_ids) {
    int idx = blockIdx.x * blockDim.x + threadIdx.x;
    const int NQE = TOKENS * NH * 32;     // q rotation pairs
    const int NKE = TOKENS * NKVH * 32;   // k rotation pairs
    if (idx >= NQE + NKE) return;
    float* base;
    int tok, j;
    bool isq = (idx < NQE);
    if (isq) {
        tok = idx >> 10;
        int r = idx & 1023;
        j = r & 31;
        base = g_q + (size_t)tok * QDIM + (r >> 5) * 64 + j;
    } else {
        int t2 = idx - NQE;
        tok = t2 >> 8;
        int r = t2 & 255;
        j = r & 31;
        base = g_k + (size_t)tok * KVDIM + (r >> 5) * 64 + j;
    }
    float p    = (float)(pos_ids[tok] + LCK_N);
    float invf = expf(-(float)j * 0.28782313662425575f);  // ln(10000)/32
    float ang  = p * invf;                                 // fp32, like reference
    float cs = (float)cos((double)ang);
    float sn = (float)sin((double)ang);
    float x1 = base[0], x2 = base[32];
    float o1 = x1 * cs - x2 * sn;
    float o2 = x2 * cs + x1 * sn;
    if (isq) { o1 *= 0.125f; o2 *= 0.125f; }
    base[0]  = o1;
    base[32] = o2;
}

// ---------------------------------------------------------------------------
// Fused flash attention with the 3 "diagonal" cache entries per row.
//   keys 0..q  : cache_k[0][b][h] with causal mask (== additive -1e9 mask)
//   extra keys : cache_k[1][b,h,q], cache_k[2][b,h,q], new rope'd k[b,kvh,q]
// Block: 64 q-rows, 32-key tiles, online softmax. 40KB STATIC shared memory
// (no dynamic smem -> no cudaFuncSetAttribute -> no device-limit mutation).
// Output written token-major into g_attn so the O projection is a plain GEMM.
// ---------------------------------------------------------------------------
#define KT 32
__global__ __launch_bounds__(256)
void flash_kernel(const float* __restrict__ cache_k, const float* __restrict__ cache_v) {
    __shared__ float qst[64 * 64];   // d-major: qst[d*64+m]          16KB
    __shared__ float kst[64 * KT];   // d-major: kst[d*KT+n]           8KB
    __shared__ float vs [KT * 64];   // n-major: vs[n*64+d]            8KB
    __shared__ float s  [64 * KT];   // scores -> probs                8KB

    const int tid = threadIdx.x;
    const int bh  = blockIdx.y;
    const int b   = bh >> 5, h = bh & 31, kvh = h >> 2;
    const int qm0 = blockIdx.x * 64;

    // load q tile (pre-scaled by rope kernel), transposed to d-major
#pragma unroll
    for (int i = tid; i < 1024; i += 256) {
        int m = i >> 4, d4 = (i & 15) * 4;
        float4 v = *(const float4*)&g_q[(size_t)(b * QLEN + qm0 + m) * QDIM + h * 64 + d4];
        qst[(d4 + 0) * 64 + m] = v.x; qst[(d4 + 1) * 64 + m] = v.y;
        qst[(d4 + 2) * 64 + m] = v.z; qst[(d4 + 3) * 64 + m] = v.w;
    }

    float acc[16];
#pragma unroll
    for (int i = 0; i < 16; i++) acc[i] = 0.f;
    float m_run = -INFINITY, l_run = 0.f;

    const int row = tid >> 2, quarter = tid & 3;   // softmax/PV mapping
    const int trow = tid >> 4, tcol = tid & 15;    // S-gemm mapping
    const int d0 = quarter * 16;                   // 16 d-values per thread
    const int c0 = quarter * 8;                    // 8 score cols per thread
    const int gq = qm0 + row;

    const float* k0p = cache_k + ((size_t)b * NH + h) * (QLEN * 64);
    const float* v0p = cache_v + ((size_t)b * NH + h) * (QLEN * 64);
    const int ntiles = 2 * (blockIdx.x + 1);       // causal: keys up to qm0+64

    for (int t = 0; t < ntiles; ++t) {
        const int kn0 = t * KT;
        __syncthreads();   // previous tile's consumers done before overwrite
        for (int i = tid; i < 512; i += 256) {
            int n = i >> 4, d4 = (i & 15) * 4;
            float4 kv = *(const float4*)&k0p[(size_t)(kn0 + n) * 64 + d4];
            kst[(d4 + 0) * KT + n] = kv.x; kst[(d4 + 1) * KT + n] = kv.y;
            kst[(d4 + 2) * KT + n] = kv.z; kst[(d4 + 3) * KT + n] = kv.w;
            float4 vv = *(const float4*)&v0p[(size_t)(kn0 + n) * 64 + d4];
            *(float4*)&vs[n * 64 + d4] = vv;
        }
        __syncthreads();

        // S = Q @ K^T  (16x16 thread grid, 4x2 micro-tile -> 64x32 scores)
        float c[4][2];
#pragma unroll
        for (int i = 0; i < 4; i++) { c[i][0] = 0.f; c[i][1] = 0.f; }
#pragma unroll 8
        for (int d = 0; d < 64; ++d) {
            float4 aq = *(const float4*)&qst[d * 64 + trow * 4];
            float2 bk = *(const float2*)&kst[d * KT + tcol * 2];
            float ar[4] = {aq.x, aq.y, aq.z, aq.w};
#pragma unroll
            for (int i = 0; i < 4; i++) {
                c[i][0] = fmaf(ar[i], bk.x, c[i][0]);
                c[i][1] = fmaf(ar[i], bk.y, c[i][1]);
            }
        }
#pragma unroll
        for (int i = 0; i < 4; i++)
            *(float2*)&s[(trow * 4 + i) * KT + tcol * 2] = make_float2(c[i][0], c[i][1]);
        __syncthreads();

        // online softmax, 4 threads per row (8 cols each)
        float pv[8];
        float tmax = -INFINITY;
#pragma unroll
        for (int j = 0; j < 8; j++) {
            int col = c0 + j;
            float sv = (kn0 + col <= gq) ? s[row * KT + col] : -INFINITY;
            pv[j] = sv;
            tmax = fmaxf(tmax, sv);
        }
        tmax = fmaxf(tmax, __shfl_xor_sync(0xffffffffu, tmax, 1));
        tmax = fmaxf(tmax, __shfl_xor_sync(0xffffffffu, tmax, 2));
        float m_new = fmaxf(m_run, tmax);
        float corr  = __expf(m_run - m_new);   // exp(-inf)=0 on first tile
        float psum  = 0.f;
#pragma unroll
        for (int j = 0; j < 8; j++) {
            float pe = __expf(pv[j] - m_new);  // masked -> exp(-inf)=0
            psum += pe;
            s[row * KT + c0 + j] = pe;
        }
        psum += __shfl_xor_sync(0xffffffffu, psum, 1);
        psum += __shfl_xor_sync(0xffffffffu, psum, 2);
        l_run = l_run * corr + psum;
        m_run = m_new;
#pragma unroll
        for (int i = 0; i < 16; i++) acc[i] *= corr;
        __syncthreads();

        // O += P @ V
#pragma unroll 4
        for (int k = 0; k < KT; k++) {
            float pw = s[row * KT + k];
            const float* vp = &vs[k * 64 + d0];
#pragma unroll
            for (int i = 0; i < 16; i += 4) {
                float4 vv = *(const float4*)(vp + i);
                acc[i + 0] = fmaf(pw, vv.x, acc[i + 0]);
                acc[i + 1] = fmaf(pw, vv.y, acc[i + 1]);
                acc[i + 2] = fmaf(pw, vv.z, acc[i + 2]);
                acc[i + 3] = fmaf(pw, vv.w, acc[i + 3]);
            }
        }
    }

    // 3 diagonal entries: cache_k[1], cache_k[2], new k (rope'd)
    const size_t tok = (size_t)b * QLEN + gq;
    const float* dk0 = cache_k + (((size_t)(1 * BATCH + b) * NH + h) * QLEN + gq) * 64;
    const float* dk1 = cache_k + (((size_t)(2 * BATCH + b) * NH + h) * QLEN + gq) * 64;
    const float* dk2 = g_k + tok * KVDIM + kvh * 64;
    const float* dv0 = cache_v + (((size_t)(1 * BATCH + b) * NH + h) * QLEN + gq) * 64;
    const float* dv1 = cache_v + (((size_t)(2 * BATCH + b) * NH + h) * QLEN + gq) * 64;
    const float* dv2 = g_v + tok * KVDIM + kvh * 64;

    float sx0 = 0.f, sx1 = 0.f, sx2 = 0.f;
#pragma unroll
    for (int j = 0; j < 16; j++) {
        float qv = qst[(d0 + j) * 64 + row];   // q pre-scaled -> scores scaled
        sx0 = fmaf(qv, dk0[d0 + j], sx0);
        sx1 = fmaf(qv, dk1[d0 + j], sx1);
        sx2 = fmaf(qv, dk2[d0 + j], sx2);
    }
    sx0 += __shfl_xor_sync(0xffffffffu, sx0, 1); sx0 += __shfl_xor_sync(0xffffffffu, sx0, 2);
    sx1 += __shfl_xor_sync(0xffffffffu, sx1, 1); sx1 += __shfl_xor_sync(0xffffffffu, sx1, 2);
    sx2 += __shfl_xor_sync(0xffffffffu, sx2, 1); sx2 += __shfl_xor_sync(0xffffffffu, sx2, 2);

    float m_new = fmaxf(fmaxf(m_run, sx0), fmaxf(sx1, sx2));
    float corr  = __expf(m_run - m_new);
    float p0 = __expf(sx0 - m_new);
    float p1 = __expf(sx1 - m_new);
    float p2 = __expf(sx2 - m_new);
    float l  = l_run * corr + p0 + p1 + p2;
    float inv = 1.f / l;

    float* op = g_attn + tok * QDIM + h * 64 + d0;
#pragma unroll
    for (int i = 0; i < 16; i += 4) {
        float4 r;
        r.x = (acc[i + 0] * corr + p0 * dv0[d0 + i + 0] + p1 * dv1[d0 + i + 0] + p2 * dv2[d0 + i + 0]) * inv;
        r.y = (acc[i + 1] * corr + p0 * dv0[d0 + i + 1] + p1 * dv1[d0 + i + 1] + p2 * dv2[d0 + i + 1]) * inv;
        r.z = (acc[i + 2] * corr + p0 * dv0[d0 + i + 2] + p1 * dv1[d0 + i + 2] + p2 * dv2[d0 + i + 2]) * inv;
        r.w = (acc[i + 3] * corr + p0 * dv0[d0 + i + 3] + p1 * dv1[d0 + i + 3] + p2 * dv2[d0 + i + 3]) * inv;
        *(float4*)(op + i) = r;
    }
}

// ---------------------------------------------------------------------------
extern "C" void kernel_launch(void* const* d_in, const int* in_sizes, int n_in,
                              void* d_out, int out_size) {
    const float* hidden  = (const float*)d_in[0];
    const float* cache_k = (const float*)d_in[1];
    const float* cache_v = (const float*)d_in[2];
    // d_in[3] attention_mask: deterministic causal (-1e9), handled analytically
    const int*   pos_ids = (const int*)d_in[4];
    const float* q_w     = (const float*)d_in[5];
    const float* k_w     = (const float*)d_in[6];
    const float* v_w     = (const float*)d_in[7];
    const float* o_w     = (const float*)d_in[8];
    float* out = (float*)d_out;

    // QKV projections
    sgemm_q_kernel<<<dim3(16, 16), 256>>>(hidden, q_w);
    sgemm_kv_kernel<<<dim3(4, 16, 2), 256>>>(hidden, k_w, v_w);

    // RoPE (+ fold 1/sqrt(D) into q)
    int nrope = TOKENS * NH * 32 + TOKENS * NKVH * 32;
    rope_kernel<<<(nrope + 255) / 256, 256>>>(pos_ids);

    // Fused attention (static 40KB smem -- no attribute calls needed)
    flash_kernel<<<dim3(16, 64), 256>>>(cache_k, cache_v);

    // Output projection -> d_out
    sgemm_o_kernel<<<dim3(16, 16), 256>>>(o_w, out);
}

// round 3
// speedup vs baseline: 1.2544x; 1.2544x over previous
#include <cuda_runtime.h>
#include <math.h>

// Problem constants
#define TOKENS 2048      // B*Q
#define HIDK   4096      // 2*HID (input feature dim)
#define QDIM   2048      // H*D
#define KVDIM  512       // KVH*D
#define NH     32
#define NKVH   8
#define LCK_N  3
#define QLEN   1024
#define BATCH  2

// Scratch (static device globals -- no allocation allowed)
__device__ float g_q[TOKENS * QDIM];      // q projection (rope'd, pre-scaled by 1/8)
__device__ float g_k[TOKENS * KVDIM];     // k projection (rope'd)
__device__ float g_v[TOKENS * KVDIM];     // v projection
__device__ float g_attn[TOKENS * QDIM];   // attention output, token-major [tok][H*D]

// ---------------------------------------------------------------------------
// TF32 helpers
// ---------------------------------------------------------------------------
__device__ __forceinline__ unsigned f2tf(float x) {
    unsigned r;
    asm("cvt.rna.tf32.f32 %0, %1;" : "=r"(r) : "f"(x));
    return r;
}

__device__ __forceinline__ void mma_tf32(float* c, const unsigned* a, const unsigned* b) {
    asm volatile(
        "mma.sync.aligned.m16n8k8.row.col.f32.tf32.tf32.f32 "
        "{%0,%1,%2,%3}, {%4,%5,%6,%7}, {%8,%9}, {%0,%1,%2,%3};\n"
        : "+f"(c[0]), "+f"(c[1]), "+f"(c[2]), "+f"(c[3])
        : "r"(a[0]), "r"(a[1]), "r"(a[2]), "r"(a[3]), "r"(b[0]), "r"(b[1]));
}

// ---------------------------------------------------------------------------
// 3xTF32 GEMM body: C[M,N] = A[M,K] @ B[N,K]^T  (fp32-accurate via hi/lo split)
// Block tile 128x128, BK=16, 256 threads = 8 warps, warp tile 64x32.
// Fragment smem layout [row][k] with stride 20 -> conflict-free LDS.
// ---------------------------------------------------------------------------
#define GK_PAD 20
__device__ __forceinline__ void gemm3tf32_body(
    const float* __restrict__ A, const float* __restrict__ Bw,
    float* __restrict__ C, int ldc, int ccol0, int K, int by)
{
    __shared__ unsigned Ah[128][GK_PAD], Al[128][GK_PAD];
    __shared__ unsigned Bh[128][GK_PAD], Bl[128][GK_PAD];

    const int tid  = threadIdx.x;
    const int wid  = tid >> 5, lane = tid & 31;
    const int mb   = (wid >> 2) * 64, nb = (wid & 3) * 32;
    const int l4   = lane >> 2, lq = lane & 3;
    const int m0   = by * 128;
    const int r0   = tid >> 2;          // loader row (0..63), +64 for 2nd half
    const int kq   = (tid & 3) * 4;     // loader k quad

    float c[16][4];
#pragma unroll
    for (int i = 0; i < 16; i++)
#pragma unroll
        for (int j = 0; j < 4; j++) c[i][j] = 0.f;

    for (int k0 = 0; k0 < K; k0 += 16) {
        __syncthreads();   // previous iter's consumers done
#pragma unroll
        for (int half = 0; half < 2; half++) {
            int row = r0 + half * 64;
            float4 v = *(const float4*)&A[(size_t)(m0 + row) * K + k0 + kq];
            unsigned h0 = f2tf(v.x), h1 = f2tf(v.y), h2 = f2tf(v.z), h3 = f2tf(v.w);
            *(uint4*)&Ah[row][kq] = make_uint4(h0, h1, h2, h3);
            *(uint4*)&Al[row][kq] = make_uint4(
                f2tf(v.x - __uint_as_float(h0)), f2tf(v.y - __uint_as_float(h1)),
                f2tf(v.z - __uint_as_float(h2)), f2tf(v.w - __uint_as_float(h3)));
            float4 w = *(const float4*)&Bw[(size_t)(ccol0 + row) * K + k0 + kq];
            unsigned g0 = f2tf(w.x), g1 = f2tf(w.y), g2 = f2tf(w.z), g3 = f2tf(w.w);
            *(uint4*)&Bh[row][kq] = make_uint4(g0, g1, g2, g3);
            *(uint4*)&Bl[row][kq] = make_uint4(
                f2tf(w.x - __uint_as_float(g0)), f2tf(w.y - __uint_as_float(g1)),
                f2tf(w.z - __uint_as_float(g2)), f2tf(w.w - __uint_as_float(g3)));
        }
        __syncthreads();

#pragma unroll
        for (int ks = 0; ks < 16; ks += 8) {
            unsigned ah[4][4], al[4][4];
#pragma unroll
            for (int mt = 0; mt < 4; mt++) {
                int r = mb + mt * 16 + l4;
                ah[mt][0] = Ah[r    ][ks + lq];     ah[mt][1] = Ah[r + 8][ks + lq];
                ah[mt][2] = Ah[r    ][ks + lq + 4]; ah[mt][3] = Ah[r + 8][ks + lq + 4];
                al[mt][0] = Al[r    ][ks + lq];     al[mt][1] = Al[r + 8][ks + lq];
                al[mt][2] = Al[r    ][ks + lq + 4]; al[mt][3] = Al[r + 8][ks + lq + 4];
            }
#pragma unroll
            for (int nt = 0; nt < 4; nt++) {
                int n = nb + nt * 8 + l4;
                unsigned bh[2] = { Bh[n][ks + lq], Bh[n][ks + lq + 4] };
                unsigned bl[2] = { Bl[n][ks + lq], Bl[n][ks + lq + 4] };
#pragma unroll
                for (int mt = 0; mt < 4; mt++) {
                    float* cc = c[mt * 4 + nt];
                    mma_tf32(cc, ah[mt], bh);   // hi*hi
                    mma_tf32(cc, ah[mt], bl);   // hi*lo
                    mma_tf32(cc, al[mt], bh);   // lo*hi
                }
            }
        }
    }

    // epilogue: c0,c1 at (row, 2*lq), c2,c3 at (row+8, 2*lq)
#pragma unroll
    for (int mt = 0; mt < 4; mt++) {
#pragma unroll
        for (int nt = 0; nt < 4; nt++) {
            const float* cc = c[mt * 4 + nt];
            int row = m0 + mb + mt * 16 + l4;
            int col = ccol0 + nb + nt * 8 + 2 * lq;
            *(float2*)&C[(size_t)row * ldc + col]       = make_float2(cc[0], cc[1]);
            *(float2*)&C[(size_t)(row + 8) * ldc + col] = make_float2(cc[2], cc[3]);
        }
    }
}

// QKV fused: grid (24, 16). Col blocks 0-15 -> q, 16-19 -> k, 20-23 -> v.
__global__ __launch_bounds__(256, 2)
void gemm_qkv_kernel(const float* __restrict__ hidden,
                     const float* __restrict__ qw, const float* __restrict__ kw,
                     const float* __restrict__ vw)
{
    int col0 = blockIdx.x * 128;
    const float* Bw; float* C; int ldc, ccol0;
    if (col0 < 2048)      { Bw = qw; C = g_q; ldc = QDIM;  ccol0 = col0; }
    else if (col0 < 2560) { Bw = kw; C = g_k; ldc = KVDIM; ccol0 = col0 - 2048; }
    else                  { Bw = vw; C = g_v; ldc = KVDIM; ccol0 = col0 - 2560; }
    gemm3tf32_body(hidden, Bw, C, ldc, ccol0, HIDK, blockIdx.y);
}

// O projection: grid (16, 16)
__global__ __launch_bounds__(256, 2)
void gemm_o_kernel(const float* __restrict__ ow, float* __restrict__ out)
{
    gemm3tf32_body(g_attn, ow, out, QDIM, blockIdx.x * 128, QDIM, blockIdx.y);
}

// ---------------------------------------------------------------------------
// RoPE (in place on g_q / g_k). Folds 1/sqrt(D)=0.125 into q.
// ---------------------------------------------------------------------------
__global__ void rope_kernel(const int* __restrict__ pos_ids) {
    int idx = blockIdx.x * blockDim.x + threadIdx.x;
    const int NQE = TOKENS * NH * 32;
    const int NKE = TOKENS * NKVH * 32;
    if (idx >= NQE + NKE) return;
    float* base;
    int tok, j;
    bool isq = (idx < NQE);
    if (isq) {
        tok = idx >> 10;
        int r = idx & 1023;
        j = r & 31;
        base = g_q + (size_t)tok * QDIM + (r >> 5) * 64 + j;
    } else {
        int t2 = idx - NQE;
        tok = t2 >> 8;
        int r = t2 & 255;
        j = r & 31;
        base = g_k + (size_t)tok * KVDIM + (r >> 5) * 64 + j;
    }
    float p    = (float)(pos_ids[tok] + LCK_N);
    float invf = expf(-(float)j * 0.28782313662425575f);  // ln(10000)/32
    float ang  = p * invf;                                 // fp32, like reference
    float cs = (float)cos((double)ang);
    float sn = (float)sin((double)ang);
    float x1 = base[0], x2 = base[32];
    float o1 = x1 * cs - x2 * sn;
    float o2 = x2 * cs + x1 * sn;
    if (isq) { o1 *= 0.125f; o2 *= 0.125f; }
    base[0]  = o1;
    base[32] = o2;
}

// ---------------------------------------------------------------------------
// Fused flash attention (unchanged from R2-pass version): 64 q-rows, 32-key
// tiles, online softmax, 3 diagonal cache entries, 40KB static smem.
// ---------------------------------------------------------------------------
#define KT 32
__global__ __launch_bounds__(256)
void flash_kernel(const float* __restrict__ cache_k, const float* __restrict__ cache_v) {
    __shared__ float qst[64 * 64];
    __shared__ float kst[64 * KT];
    __shared__ float vs [KT * 64];
    __shared__ float s  [64 * KT];

    const int tid = threadIdx.x;
    const int bh  = blockIdx.y;
    const int b   = bh >> 5, h = bh & 31, kvh = h >> 2;
    const int qm0 = blockIdx.x * 64;

#pragma unroll
    for (int i = tid; i < 1024; i += 256) {
        int m = i >> 4, d4 = (i & 15) * 4;
        float4 v = *(const float4*)&g_q[(size_t)(b * QLEN + qm0 + m) * QDIM + h * 64 + d4];
        qst[(d4 + 0) * 64 + m] = v.x; qst[(d4 + 1) * 64 + m] = v.y;
        qst[(d4 + 2) * 64 + m] = v.z; qst[(d4 + 3) * 64 + m] = v.w;
    }

    float acc[16];
#pragma unroll
    for (int i = 0; i < 16; i++) acc[i] = 0.f;
    float m_run = -INFINITY, l_run = 0.f;

    const int row = tid >> 2, quarter = tid & 3;
    const int trow = tid >> 4, tcol = tid & 15;
    const int d0 = quarter * 16;
    const int c0 = quarter * 8;
    const int gq = qm0 + row;

    const float* k0p = cache_k + ((size_t)b * NH + h) * (QLEN * 64);
    const float* v0p = cache_v + ((size_t)b * NH + h) * (QLEN * 64);
    const int ntiles = 2 * (blockIdx.x + 1);

    for (int t = 0; t < ntiles; ++t) {
        const int kn0 = t * KT;
        __syncthreads();
        for (int i = tid; i < 512; i += 256) {
            int n = i >> 4, d4 = (i & 15) * 4;
            float4 kv = *(const float4*)&k0p[(size_t)(kn0 + n) * 64 + d4];
            kst[(d4 + 0) * KT + n] = kv.x; kst[(d4 + 1) * KT + n] = kv.y;
            kst[(d4 + 2) * KT + n] = kv.z; kst[(d4 + 3) * KT + n] = kv.w;
            float4 vv = *(const float4*)&v0p[(size_t)(kn0 + n) * 64 + d4];
            *(float4*)&vs[n * 64 + d4] = vv;
        }
        __syncthreads();

        float c[4][2];
#pragma unroll
        for (int i = 0; i < 4; i++) { c[i][0] = 0.f; c[i][1] = 0.f; }
#pragma unroll 8
        for (int d = 0; d < 64; ++d) {
            float4 aq = *(const float4*)&qst[d * 64 + trow * 4];
            float2 bk = *(const float2*)&kst[d * KT + tcol * 2];
            float ar[4] = {aq.x, aq.y, aq.z, aq.w};
#pragma unroll
            for (int i = 0; i < 4; i++) {
                c[i][0] = fmaf(ar[i], bk.x, c[i][0]);
                c[i][1] = fmaf(ar[i], bk.y, c[i][1]);
            }
        }
#pragma unroll
        for (int i = 0; i < 4; i++)
            *(float2*)&s[(trow * 4 + i) * KT + tcol * 2] = make_float2(c[i][0], c[i][1]);
        __syncthreads();

        float pv[8];
        float tmax = -INFINITY;
#pragma unroll
        for (int j = 0; j < 8; j++) {
            int col = c0 + j;
            float sv = (kn0 + col <= gq) ? s[row * KT + col] : -INFINITY;
            pv[j] = sv;
            tmax = fmaxf(tmax, sv);
        }
        tmax = fmaxf(tmax, __shfl_xor_sync(0xffffffffu, tmax, 1));
        tmax = fmaxf(tmax, __shfl_xor_sync(0xffffffffu, tmax, 2));
        float m_new = fmaxf(m_run, tmax);
        float corr  = __expf(m_run - m_new);
        float psum  = 0.f;
#pragma unroll
        for (int j = 0; j < 8; j++) {
            float pe = __expf(pv[j] - m_new);
            psum += pe;
            s[row * KT + c0 + j] = pe;
        }
        psum += __shfl_xor_sync(0xffffffffu, psum, 1);
        psum += __shfl_xor_sync(0xffffffffu, psum, 2);
        l_run = l_run * corr + psum;
        m_run = m_new;
#pragma unroll
        for (int i = 0; i < 16; i++) acc[i] *= corr;
        __syncthreads();

#pragma unroll 4
        for (int k = 0; k < KT; k++) {
            float pw = s[row * KT + k];
            const float* vp = &vs[k * 64 + d0];
#pragma unroll
            for (int i = 0; i < 16; i += 4) {
                float4 vv = *(const float4*)(vp + i);
                acc[i + 0] = fmaf(pw, vv.x, acc[i + 0]);
                acc[i + 1] = fmaf(pw, vv.y, acc[i + 1]);
                acc[i + 2] = fmaf(pw, vv.z, acc[i + 2]);
                acc[i + 3] = fmaf(pw, vv.w, acc[i + 3]);
            }
        }
    }

    const size_t tok = (size_t)b * QLEN + gq;
    const float* dk0 = cache_k + (((size_t)(1 * BATCH + b) * NH + h) * QLEN + gq) * 64;
    const float* dk1 = cache_k + (((size_t)(2 * BATCH + b) * NH + h) * QLEN + gq) * 64;
    const float* dk2 = g_k + tok * KVDIM + kvh * 64;
    const float* dv0 = cache_v + (((size_t)(1 * BATCH + b) * NH + h) * QLEN + gq) * 64;
    const float* dv1 = cache_v + (((size_t)(2 * BATCH + b) * NH + h) * QLEN + gq) * 64;
    const float* dv2 = g_v + tok * KVDIM + kvh * 64;

    float sx0 = 0.f, sx1 = 0.f, sx2 = 0.f;
#pragma unroll
    for (int j = 0; j < 16; j++) {
        float qv = qst[(d0 + j) * 64 + row];
        sx0 = fmaf(qv, dk0[d0 + j], sx0);
        sx1 = fmaf(qv, dk1[d0 + j], sx1);
        sx2 = fmaf(qv, dk2[d0 + j], sx2);
    }
    sx0 += __shfl_xor_sync(0xffffffffu, sx0, 1); sx0 += __shfl_xor_sync(0xffffffffu, sx0, 2);
    sx1 += __shfl_xor_sync(0xffffffffu, sx1, 1); sx1 += __shfl_xor_sync(0xffffffffu, sx1, 2);
    sx2 += __shfl_xor_sync(0xffffffffu, sx2, 1); sx2 += __shfl_xor_sync(0xffffffffu, sx2, 2);

    float m_new = fmaxf(fmaxf(m_run, sx0), fmaxf(sx1, sx2));
    float corr  = __expf(m_run - m_new);
    float p0 = __expf(sx0 - m_new);
    float p1 = __expf(sx1 - m_new);
    float p2 = __expf(sx2 - m_new);
    float l  = l_run * corr + p0 + p1 + p2;
    float inv = 1.f / l;

    float* op = g_attn + tok * QDIM + h * 64 + d0;
#pragma unroll
    for (int i = 0; i < 16; i += 4) {
        float4 r;
        r.x = (acc[i + 0] * corr + p0 * dv0[d0 + i + 0] + p1 * dv1[d0 + i + 0] + p2 * dv2[d0 + i + 0]) * inv;
        r.y = (acc[i + 1] * corr + p0 * dv0[d0 + i + 1] + p1 * dv1[d0 + i + 1] + p2 * dv2[d0 + i + 1]) * inv;
        r.z = (acc[i + 2] * corr + p0 * dv0[d0 + i + 2] + p1 * dv1[d0 + i + 2] + p2 * dv2[d0 + i + 2]) * inv;
        r.w = (acc[i + 3] * corr + p0 * dv0[d0 + i + 3] + p1 * dv1[d0 + i + 3] + p2 * dv2[d0 + i + 3]) * inv;
        *(float4*)(op + i) = r;
    }
}

// ---------------------------------------------------------------------------
extern "C" void kernel_launch(void* const* d_in, const int* in_sizes, int n_in,
                              void* d_out, int out_size) {
    const float* hidden  = (const float*)d_in[0];
    const float* cache_k = (const float*)d_in[1];
    const float* cache_v = (const float*)d_in[2];
    // d_in[3] attention_mask: deterministic causal (-1e9), handled analytically
    const int*   pos_ids = (const int*)d_in[4];
    const float* q_w     = (const float*)d_in[5];
    const float* k_w     = (const float*)d_in[6];
    const float* v_w     = (const float*)d_in[7];
    const float* o_w     = (const float*)d_in[8];
    float* out = (float*)d_out;

    // QKV projections (3xTF32 tensor cores, fused into one launch)
    gemm_qkv_kernel<<<dim3(24, 16), 256>>>(hidden, q_w, k_w, v_w);

    // RoPE (+ fold 1/sqrt(D) into q)
    int nrope = TOKENS * NH * 32 + TOKENS * NKVH * 32;
    rope_kernel<<<(nrope + 255) / 256, 256>>>(pos_ids);

    // Fused attention
    flash_kernel<<<dim3(16, 64), 256>>>(cache_k, cache_v);

    // Output projection -> d_out (3xTF32)
    gemm_o_kernel<<<dim3(16, 16), 256>>>(o_w, out);
}

// round 4
// speedup vs baseline: 2.0727x; 1.6523x over previous
#include <cuda_runtime.h>
#include <math.h>

// Problem constants
#define TOKENS 2048      // B*Q
#define HIDK   4096      // 2*HID (input feature dim)
#define QDIM   2048      // H*D
#define KVDIM  512       // KVH*D
#define NH     32
#define NKVH   8
#define LCK_N  3
#define QLEN   1024
#define BATCH  2

// Scratch (static device globals -- no allocation allowed)
__device__ float g_q[TOKENS * QDIM];      // q projection (rope'd, pre-scaled by 1/8)
__device__ float g_k[TOKENS * KVDIM];     // k projection (rope'd)
__device__ float g_v[TOKENS * KVDIM];     // v projection
__device__ float g_attn[TOKENS * QDIM];   // attention output, token-major [tok][H*D]

// ---------------------------------------------------------------------------
// TF32 helpers
// ---------------------------------------------------------------------------
__device__ __forceinline__ unsigned f2tf(float x) {
    unsigned r;
    asm("cvt.rna.tf32.f32 %0, %1;" : "=r"(r) : "f"(x));
    return r;
}
__device__ __forceinline__ float tf32r(float x) {        // rounded fp32 pattern
    return __uint_as_float(f2tf(x));
}

__device__ __forceinline__ void mma_tf32(float* c, const unsigned* a, const unsigned* b) {
    asm volatile(
        "mma.sync.aligned.m16n8k8.row.col.f32.tf32.tf32.f32 "
        "{%0,%1,%2,%3}, {%4,%5,%6,%7}, {%8,%9}, {%0,%1,%2,%3};\n"
        : "+f"(c[0]), "+f"(c[1]), "+f"(c[2]), "+f"(c[3])
        : "r"(a[0]), "r"(a[1]), "r"(a[2]), "r"(a[3]), "r"(b[0]), "r"(b[1]));
}

// ---------------------------------------------------------------------------
// 3xTF32 GEMM body with register-prefetch pipelining.
// C[M,N] = A[M,K] @ B[N,K]^T. Block 128x128, BK=16, 8 warps, warp tile 64x32.
// ---------------------------------------------------------------------------
#define GK_PAD 20
__device__ __forceinline__ void sts_split(float4 v, unsigned* hi, unsigned* lo) {
    unsigned h0 = f2tf(v.x), h1 = f2tf(v.y), h2 = f2tf(v.z), h3 = f2tf(v.w);
    *(uint4*)hi = make_uint4(h0, h1, h2, h3);
    *(uint4*)lo = make_uint4(
        f2tf(v.x - __uint_as_float(h0)), f2tf(v.y - __uint_as_float(h1)),
        f2tf(v.z - __uint_as_float(h2)), f2tf(v.w - __uint_as_float(h3)));
}

__device__ __forceinline__ void gemm3tf32_body(
    const float* __restrict__ A, const float* __restrict__ Bw,
    float* __restrict__ C, int ldc, int ccol0, int K, int by)
{
    __shared__ unsigned Ah[128][GK_PAD], Al[128][GK_PAD];
    __shared__ unsigned Bh[128][GK_PAD], Bl[128][GK_PAD];

    const int tid  = threadIdx.x;
    const int wid  = tid >> 5, lane = tid & 31;
    const int mb   = (wid >> 2) * 64, nb = (wid & 3) * 32;
    const int l4   = lane >> 2, lq = lane & 3;
    const int m0   = by * 128;
    const int r0   = tid >> 2;
    const int kq   = (tid & 3) * 4;

    float c[16][4];
#pragma unroll
    for (int i = 0; i < 16; i++)
#pragma unroll
        for (int j = 0; j < 4; j++) c[i][j] = 0.f;

    const float* Ap0 = A  + (size_t)(m0 + r0) * K + kq;
    const float* Ap1 = Ap0 + (size_t)64 * K;
    const float* Bp0 = Bw + (size_t)(ccol0 + r0) * K + kq;
    const float* Bp1 = Bp0 + (size_t)64 * K;

    float4 av0 = *(const float4*)Ap0;
    float4 av1 = *(const float4*)Ap1;
    float4 bv0 = *(const float4*)Bp0;
    float4 bv1 = *(const float4*)Bp1;

    for (int k0 = 0; k0 < K; k0 += 16) {
        sts_split(av0, &Ah[r0][kq],      &Al[r0][kq]);
        sts_split(av1, &Ah[r0 + 64][kq], &Al[r0 + 64][kq]);
        sts_split(bv0, &Bh[r0][kq],      &Bl[r0][kq]);
        sts_split(bv1, &Bh[r0 + 64][kq], &Bl[r0 + 64][kq]);
        __syncthreads();
        if (k0 + 16 < K) {                      // prefetch overlaps with mma
            av0 = *(const float4*)(Ap0 + k0 + 16);
            av1 = *(const float4*)(Ap1 + k0 + 16);
            bv0 = *(const float4*)(Bp0 + k0 + 16);
            bv1 = *(const float4*)(Bp1 + k0 + 16);
        }
#pragma unroll
        for (int ks = 0; ks < 16; ks += 8) {
            unsigned ah[4][4], al[4][4];
#pragma unroll
            for (int mt = 0; mt < 4; mt++) {
                int r = mb + mt * 16 + l4;
                ah[mt][0] = Ah[r    ][ks + lq];     ah[mt][1] = Ah[r + 8][ks + lq];
                ah[mt][2] = Ah[r    ][ks + lq + 4]; ah[mt][3] = Ah[r + 8][ks + lq + 4];
                al[mt][0] = Al[r    ][ks + lq];     al[mt][1] = Al[r + 8][ks + lq];
                al[mt][2] = Al[r    ][ks + lq + 4]; al[mt][3] = Al[r + 8][ks + lq + 4];
            }
#pragma unroll
            for (int nt = 0; nt < 4; nt++) {
                int n = nb + nt * 8 + l4;
                unsigned bh[2] = { Bh[n][ks + lq], Bh[n][ks + lq + 4] };
                unsigned bl[2] = { Bl[n][ks + lq], Bl[n][ks + lq + 4] };
#pragma unroll
                for (int mt = 0; mt < 4; mt++) {
                    float* cc = c[mt * 4 + nt];
                    mma_tf32(cc, ah[mt], bh);
                    mma_tf32(cc, ah[mt], bl);
                    mma_tf32(cc, al[mt], bh);
                }
            }
        }
        __syncthreads();
    }

#pragma unroll
    for (int mt = 0; mt < 4; mt++) {
#pragma unroll
        for (int nt = 0; nt < 4; nt++) {
            const float* cc = c[mt * 4 + nt];
            int row = m0 + mb + mt * 16 + l4;
            int col = ccol0 + nb + nt * 8 + 2 * lq;
            *(float2*)&C[(size_t)row * ldc + col]       = make_float2(cc[0], cc[1]);
            *(float2*)&C[(size_t)(row + 8) * ldc + col] = make_float2(cc[2], cc[3]);
        }
    }
}

__global__ __launch_bounds__(256, 2)
void gemm_qkv_kernel(const float* __restrict__ hidden,
                     const float* __restrict__ qw, const float* __restrict__ kw,
                     const float* __restrict__ vw)
{
    int col0 = blockIdx.x * 128;
    const float* Bw; float* C; int ldc, ccol0;
    if (col0 < 2048)      { Bw = qw; C = g_q; ldc = QDIM;  ccol0 = col0; }
    else if (col0 < 2560) { Bw = kw; C = g_k; ldc = KVDIM; ccol0 = col0 - 2048; }
    else                  { Bw = vw; C = g_v; ldc = KVDIM; ccol0 = col0 - 2560; }
    gemm3tf32_body(hidden, Bw, C, ldc, ccol0, HIDK, blockIdx.y);
}

__global__ __launch_bounds__(256, 2)
void gemm_o_kernel(const float* __restrict__ ow, float* __restrict__ out)
{
    gemm3tf32_body(g_attn, ow, out, QDIM, blockIdx.x * 128, QDIM, blockIdx.y);
}

// ---------------------------------------------------------------------------
// RoPE (in place on g_q / g_k). Folds 1/sqrt(D)=0.125 into q.
// ---------------------------------------------------------------------------
__global__ void rope_kernel(const int* __restrict__ pos_ids) {
    int idx = blockIdx.x * blockDim.x + threadIdx.x;
    const int NQE = TOKENS * NH * 32;
    const int NKE = TOKENS * NKVH * 32;
    if (idx >= NQE + NKE) return;
    float* base;
    int tok, j;
    bool isq = (idx < NQE);
    if (isq) {
        tok = idx >> 10;
        int r = idx & 1023;
        j = r & 31;
        base = g_q + (size_t)tok * QDIM + (r >> 5) * 64 + j;
    } else {
        int t2 = idx - NQE;
        tok = t2 >> 8;
        int r = t2 & 255;
        j = r & 31;
        base = g_k + (size_t)tok * KVDIM + (r >> 5) * 64 + j;
    }
    float p    = (float)(pos_ids[tok] + LCK_N);
    float invf = expf(-(float)j * 0.28782313662425575f);  // ln(10000)/32
    float ang  = p * invf;
    float cs = (float)cos((double)ang);
    float sn = (float)sin((double)ang);
    float x1 = base[0], x2 = base[32];
    float o1 = x1 * cs - x2 * sn;
    float o2 = x2 * cs + x1 * sn;
    if (isq) { o1 *= 0.125f; o2 *= 0.125f; }
    base[0]  = o1;
    base[32] = o2;
}

// ---------------------------------------------------------------------------
// Tensor-core flash attention. 128 q-rows/block, 8 warps (m16 each), 32-key
// tiles. S and PV via mma.m16n8k8.tf32; online softmax in accum layout;
// 3 diagonal cache entries in fp32 tail. ~36KB static smem.
// ---------------------------------------------------------------------------
#define FKT 32
#define NEG_BIG (-1e30f)
__global__ __launch_bounds__(256)
void flash_kernel(const float* __restrict__ cache_k, const float* __restrict__ cache_v) {
    __shared__ float kst[FKT][68];    // n-major K tile (tf32-rounded)
    __shared__ float vst[FKT][72];    // n-major V tile (tf32-rounded)
    __shared__ float ps [128][36];    // P probs (tf32-rounded), per-warp rows

    const int tid  = threadIdx.x;
    const int wid  = tid >> 5, lane = tid & 31;
    const int l4   = lane >> 2, lq = lane & 3;
    const int bh   = blockIdx.y;
    const int b    = bh >> 5, h = bh & 31, kvh = h >> 2;
    const int qm0  = blockIdx.x * 128;
    const int rlo  = wid * 16 + l4;        // block-local rows
    const int rhi  = rlo + 8;
    const int gqlo = qm0 + rlo, gqhi = qm0 + rhi;

    // Q fragments (tf32), held in registers for the whole kernel
    unsigned qf[8][4];
    {
        const float* qlo = &g_q[(size_t)(b * QLEN + gqlo) * QDIM + h * 64];
        const float* qhi = &g_q[(size_t)(b * QLEN + gqhi) * QDIM + h * 64];
#pragma unroll
        for (int ks = 0; ks < 8; ks++) {
            qf[ks][0] = f2tf(qlo[ks * 8 + lq]);
            qf[ks][1] = f2tf(qhi[ks * 8 + lq]);
            qf[ks][2] = f2tf(qlo[ks * 8 + lq + 4]);
            qf[ks][3] = f2tf(qhi[ks * 8 + lq + 4]);
        }
    }

    float o[8][4];
#pragma unroll
    for (int i = 0; i < 8; i++)
#pragma unroll
        for (int j = 0; j < 4; j++) o[i][j] = 0.f;
    float mlo = NEG_BIG, mhi = NEG_BIG, llo = 0.f, lhi = 0.f;

    const float* k0p = cache_k + ((size_t)b * NH + h) * (QLEN * 64);
    const float* v0p = cache_v + ((size_t)b * NH + h) * (QLEN * 64);
    const int ntiles = 4 * (blockIdx.x + 1);

    for (int t = 0; t < ntiles; ++t) {
        const int kn0 = t * FKT;
        __syncthreads();
        for (int i = tid; i < 512; i += 256) {
            int n = i >> 4, d4 = (i & 15) * 4;
            float4 kv = *(const float4*)&k0p[(size_t)(kn0 + n) * 64 + d4];
            kst[n][d4 + 0] = tf32r(kv.x); kst[n][d4 + 1] = tf32r(kv.y);
            kst[n][d4 + 2] = tf32r(kv.z); kst[n][d4 + 3] = tf32r(kv.w);
            float4 vv = *(const float4*)&v0p[(size_t)(kn0 + n) * 64 + d4];
            vst[n][d4 + 0] = tf32r(vv.x); vst[n][d4 + 1] = tf32r(vv.y);
            vst[n][d4 + 2] = tf32r(vv.z); vst[n][d4 + 3] = tf32r(vv.w);
        }
        __syncthreads();

        // S = Q @ K^T
        float sc[4][4];
#pragma unroll
        for (int nt = 0; nt < 4; nt++)
#pragma unroll
            for (int j = 0; j < 4; j++) sc[nt][j] = 0.f;
#pragma unroll
        for (int ks = 0; ks < 8; ks++) {
#pragma unroll
            for (int nt = 0; nt < 4; nt++) {
                unsigned bf[2];
                bf[0] = __float_as_uint(kst[nt * 8 + l4][ks * 8 + lq]);
                bf[1] = __float_as_uint(kst[nt * 8 + l4][ks * 8 + lq + 4]);
                mma_tf32(sc[nt], qf[ks], bf);
            }
        }

        // causal mask + row maxima
        float tmaxlo = NEG_BIG, tmaxhi = NEG_BIG;
#pragma unroll
        for (int nt = 0; nt < 4; nt++) {
            int cn = kn0 + nt * 8 + 2 * lq;
            if (cn     > gqlo) sc[nt][0] = NEG_BIG;
            if (cn + 1 > gqlo) sc[nt][1] = NEG_BIG;
            if (cn     > gqhi) sc[nt][2] = NEG_BIG;
            if (cn + 1 > gqhi) sc[nt][3] = NEG_BIG;
            tmaxlo = fmaxf(tmaxlo, fmaxf(sc[nt][0], sc[nt][1]));
            tmaxhi = fmaxf(tmaxhi, fmaxf(sc[nt][2], sc[nt][3]));
        }
        tmaxlo = fmaxf(tmaxlo, __shfl_xor_sync(0xffffffffu, tmaxlo, 1));
        tmaxlo = fmaxf(tmaxlo, __shfl_xor_sync(0xffffffffu, tmaxlo, 2));
        tmaxhi = fmaxf(tmaxhi, __shfl_xor_sync(0xffffffffu, tmaxhi, 1));
        tmaxhi = fmaxf(tmaxhi, __shfl_xor_sync(0xffffffffu, tmaxhi, 2));

        float mnlo = fmaxf(mlo, tmaxlo), mnhi = fmaxf(mhi, tmaxhi);
        float corlo = __expf(mlo - mnlo), corhi = __expf(mhi - mnhi);

        float psumlo = 0.f, psumhi = 0.f;
#pragma unroll
        for (int nt = 0; nt < 4; nt++) {
            float p0 = __expf(sc[nt][0] - mnlo);
            float p1 = __expf(sc[nt][1] - mnlo);
            float p2 = __expf(sc[nt][2] - mnhi);
            float p3 = __expf(sc[nt][3] - mnhi);
            psumlo += p0 + p1;
            psumhi += p2 + p3;
            *(float2*)&ps[rlo][nt * 8 + 2 * lq] = make_float2(tf32r(p0), tf32r(p1));
            *(float2*)&ps[rhi][nt * 8 + 2 * lq] = make_float2(tf32r(p2), tf32r(p3));
        }
        psumlo += __shfl_xor_sync(0xffffffffu, psumlo, 1);
        psumlo += __shfl_xor_sync(0xffffffffu, psumlo, 2);
        psumhi += __shfl_xor_sync(0xffffffffu, psumhi, 1);
        psumhi += __shfl_xor_sync(0xffffffffu, psumhi, 2);
        llo = llo * corlo + psumlo;
        lhi = lhi * corhi + psumhi;
        mlo = mnlo; mhi = mnhi;

#pragma unroll
        for (int dt = 0; dt < 8; dt++) {
            o[dt][0] *= corlo; o[dt][1] *= corlo;
            o[dt][2] *= corhi; o[dt][3] *= corhi;
        }
        __syncwarp();

        // O += P @ V   (A = P from smem, B = V^T fragments from n-major vst)
#pragma unroll
        for (int ks = 0; ks < 4; ks++) {
            unsigned af[4];
            af[0] = __float_as_uint(ps[rlo][ks * 8 + lq]);
            af[1] = __float_as_uint(ps[rhi][ks * 8 + lq]);
            af[2] = __float_as_uint(ps[rlo][ks * 8 + lq + 4]);
            af[3] = __float_as_uint(ps[rhi][ks * 8 + lq + 4]);
#pragma unroll
            for (int dt = 0; dt < 8; dt++) {
                unsigned bf[2];
                bf[0] = __float_as_uint(vst[ks * 8 + lq    ][dt * 8 + l4]);
                bf[1] = __float_as_uint(vst[ks * 8 + lq + 4][dt * 8 + l4]);
                mma_tf32(o[dt], af, bf);
            }
        }
    }

    // ---- tail: 3 diagonal entries (fp32) + normalize + writeout ----
#pragma unroll
    for (int half = 0; half < 2; half++) {
        int   R     = half ? gqhi : gqlo;
        float m_run = half ? mhi : mlo;
        float l_run = half ? lhi : llo;
        int   ci    = half ? 2 : 0;

        const size_t tok = (size_t)b * QLEN + R;
        const float* dk0 = cache_k + (((size_t)(BATCH + b) * NH + h) * QLEN + R) * 64;
        const float* dk1 = cache_k + (((size_t)(2 * BATCH + b) * NH + h) * QLEN + R) * 64;
        const float* dk2 = g_k + tok * KVDIM + kvh * 64;
        const float* dv0 = cache_v + (((size_t)(BATCH + b) * NH + h) * QLEN + R) * 64;
        const float* dv1 = cache_v + (((size_t)(2 * BATCH + b) * NH + h) * QLEN + R) * 64;
        const float* dv2 = g_v + tok * KVDIM + kvh * 64;
        const float* qr  = &g_q[tok * QDIM + h * 64];

        float sx0 = 0.f, sx1 = 0.f, sx2 = 0.f;
#pragma unroll
        for (int j = 0; j < 16; j++) {
            int d = lq * 16 + j;
            float qv = qr[d];
            sx0 = fmaf(qv, dk0[d], sx0);
            sx1 = fmaf(qv, dk1[d], sx1);
            sx2 = fmaf(qv, dk2[d], sx2);
        }
        sx0 += __shfl_xor_sync(0xffffffffu, sx0, 1); sx0 += __shfl_xor_sync(0xffffffffu, sx0, 2);
        sx1 += __shfl_xor_sync(0xffffffffu, sx1, 1); sx1 += __shfl_xor_sync(0xffffffffu, sx1, 2);
        sx2 += __shfl_xor_sync(0xffffffffu, sx2, 1); sx2 += __shfl_xor_sync(0xffffffffu, sx2, 2);

        float mn  = fmaxf(fmaxf(m_run, sx0), fmaxf(sx1, sx2));
        float cor = __expf(m_run - mn);
        float p0  = __expf(sx0 - mn);
        float p1  = __expf(sx1 - mn);
        float p2  = __expf(sx2 - mn);
        float inv = 1.f / (l_run * cor + p0 + p1 + p2);

        float* op = g_attn + tok * QDIM + h * 64;
#pragma unroll
        for (int dt = 0; dt < 8; dt++) {
            int d = dt * 8 + 2 * lq;
            float x = (o[dt][ci]     * cor + p0 * dv0[d]     + p1 * dv1[d]     + p2 * dv2[d])     * inv;
            float y = (o[dt][ci + 1] * cor + p0 * dv0[d + 1] + p1 * dv1[d + 1] + p2 * dv2[d + 1]) * inv;
            *(float2*)&op[d] = make_float2(x, y);
        }
    }
}

// ---------------------------------------------------------------------------
extern "C" void kernel_launch(void* const* d_in, const int* in_sizes, int n_in,
                              void* d_out, int out_size) {
    const float* hidden  = (const float*)d_in[0];
    const float* cache_k = (const float*)d_in[1];
    const float* cache_v = (const float*)d_in[2];
    const int*   pos_ids = (const int*)d_in[4];
    const float* q_w     = (const float*)d_in[5];
    const float* k_w     = (const float*)d_in[6];
    const float* v_w     = (const float*)d_in[7];
    const float* o_w     = (const float*)d_in[8];
    float* out = (float*)d_out;

    gemm_qkv_kernel<<<dim3(24, 16), 256>>>(hidden, q_w, k_w, v_w);

    int nrope = TOKENS * NH * 32 + TOKENS * NKVH * 32;
    rope_kernel<<<(nrope + 255) / 256, 256>>>(pos_ids);

    flash_kernel<<<dim3(8, 64), 256>>>(cache_k, cache_v);

    gemm_o_kernel<<<dim3(16, 16), 256>>>(o_w, out);
}